// round 12
// baseline (speedup 1.0000x reference)
#include <cuda_runtime.h>
#include <cstdint>
#include <math.h>

// SoftPolygon B=32, P=32, 128x128.  out[b,y,x] = sigmoid(min_seg_sq * io)
//
// v12: warp = full row (4 px/lane), exact segment-segment cull.
//      Halves warp count (4096) to halve duplicated fixed costs (precompute,
//      cull, parity, epilogue). Intersection part of the cull reuses the
//      parity xint of the neighboring lane via one shfl (exact crossing-x of
//      this lane's distance edge). Culled edges are >5px from every pixel in
//      the row -> sigmoid saturated within 1.4e-11 << 1e-3.
//
// Numerical contract: parity bit-identical to reference via integer-threshold
// + XOR-mask (exact-op-order division); distance path continuous (ulp error).

namespace {

constexpr int NB  = 32;
constexpr int NP  = 32;
constexpr int NH  = 128;
constexpr int NW  = 128;
constexpr int RPB = 4;            // rows per block (warp = row)
constexpr float CULL_T = 25.0f;   // squared-distance saturation threshold

__global__ __launch_bounds__(128) void soft_poly_kernel(
    const float* __restrict__ verts,   // (B, P, 2)
    float* __restrict__ out)           // (B, H, W)
{
    const int b    = blockIdx.y;
    const int row0 = blockIdx.x * RPB;
    const int tid  = threadIdx.x;
    const int w    = tid >> 5;         // warp index = local row
    const int lane = tid & 31;
    const int row  = row0 + w;
    const float gy = (float)row;

    __shared__ float  vbuf[NP * 2];    // interleaved x,y
    __shared__ float4 sA[RPB][NP];     // {x1, dx*inv, ys1*dy*inv, dx}
    __shared__ float2 sB[RPB][NP];     // {dy, ys1}

    if (tid < NP * 2) vbuf[tid] = verts[(size_t)b * NP * 2 + tid];
    __syncthreads();

    // ---- per-(row, edge) precompute; edge = lane; warp-local ----
    const unsigned full = 0xffffffffu;
    unsigned int pm0, pm1, pm2, pm3;   // parity words, cols [32k, 32k+32)
    unsigned int bits;                 // keep-mask of relevant edges
    {
        const int i  = lane;
        const int jp = (i + NP - 1) & (NP - 1);   // prev vertex (roll +1)
        const int kn = (i + 1) & (NP - 1);        // next vertex (roll -1)
        const float fx = vbuf[2 * i],  fy = vbuf[2 * i + 1];
        const float tx = vbuf[2 * jp], ty = vbuf[2 * jp + 1];
        const float x2 = vbuf[2 * kn], y2 = vbuf[2 * kn + 1];

        // crossing threshold, EXACT reference op order (mul, div, add)
        const bool cond = (fy > gy) != (ty > gy);
        float xint = __fadd_rn(
            __fdiv_rn(__fmul_rn(tx - fx, gy - fy), ty - fy), fx);
        // crossing of parity-edge (jp->i) with the row segment x in [0,127]:
        // this IS the distance edge of lane jp; share via shfl below.
        const bool crossFlag = cond && (xint >= 0.0f) && (xint <= 127.0f);
        if (!cond) xint = -1.0f;
        // #columns c in [0,128) with (float)c < xint — exact
        const float xc = fminf(fmaxf(ceilf(xint), 0.0f), 128.0f);
        const int ci = (int)xc;

        const int n0 = min(max(ci,      0), 32);
        const int n1 = min(max(ci - 32, 0), 32);
        const int n2 = min(max(ci - 64, 0), 32);
        const int n3 = min(max(ci - 96, 0), 32);
        const unsigned int m0 = (unsigned int)((1ull << n0) - 1ull);
        const unsigned int m1 = (unsigned int)((1ull << n1) - 1ull);
        const unsigned int m2 = (unsigned int)((1ull << n2) - 1ull);
        const unsigned int m3 = (unsigned int)((1ull << n3) - 1ull);
        pm0 = __reduce_xor_sync(full, m0);
        pm1 = __reduce_xor_sync(full, m1);
        pm2 = __reduce_xor_sync(full, m2);
        pm3 = __reduce_xor_sync(full, m3);

        // segment-distance constants for edge (v_i -> v_{i+1})
        const float dx = x2 - fx, dy = y2 - fy;
        const float sq  = dx * dx + dy * dy + 1e-5f;
        const float inv = __fdiv_rn(1.0f, sq);
        const float ys1 = gy - fy;
        const float ys2 = gy - y2;
        sA[w][i] = make_float4(fx, dx * inv, ys1 * dy * inv, dx);
        sB[w][i] = make_float2(dy, ys1);

        // ---- EXACT cull: dist(row segment [0,127]x{gy}, edge)^2 <= 25 ----
        // (1) edge endpoints -> row segment
        const float ga  = fmaxf(0.0f, fmaxf(-fx, fx - 127.0f));
        const float gb  = fmaxf(0.0f, fmaxf(-x2, x2 - 127.0f));
        const float dva = fmaf(ga, ga, ys1 * ys1);
        const float dvb = fmaf(gb, gb, ys2 * ys2);
        // (2) row endpoints (0,gy), (127,gy) -> edge
        float dpa, dpb;
        {
            const float xsA = 0.0f - fx;
            const float tA  = __saturatef((xsA * dx + ys1 * dy) * inv);
            const float xpA = fmaf(-tA, dx, xsA);
            const float ypA = fmaf(-tA, dy, ys1);
            dpa = fmaf(xpA, xpA, ypA * ypA);
            const float xsB = 127.0f - fx;
            const float tB  = __saturatef((xsB * dx + ys1 * dy) * inv);
            const float xpB = fmaf(-tB, dx, xsB);
            const float ypB = fmaf(-tB, dy, ys1);
            dpb = fmaf(xpB, xpB, ypB * ypB);
        }
        // (3) intersection: crossFlag of lane (i+1) is for edge (i -> i+1)
        const bool isect =
            (bool)__shfl_sync(full, (int)crossFlag, (lane + 1) & 31);

        const float best = fminf(fminf(dva, dvb), fminf(dpa, dpb));
        bits = __ballot_sync(full, isect || (best <= CULL_T));
    }
    __syncwarp();   // sA/sB written and read by the same warp

    // ---- mainloop: surviving edges only, 4 pixels per lane ----
    const float gx0 = (float)lane;
    const float gx1 = gx0 + 32.0f;
    const float gx2 = gx0 + 64.0f;
    const float gx3 = gx0 + 96.0f;
    float mn0 = 3.402823466e38f, mn1 = mn0, mn2 = mn0, mn3 = mn0;

    while (bits) {
        const int i = __ffs(bits) - 1;
        bits &= bits - 1;
        const float4 a  = sA[w][i];
        const float2 bb = sB[w][i];

#define PIX(GX, MN) do {                                   \
        const float xs  = (GX) - a.x;                      \
        const float dot = fmaf(xs, a.y, a.z);              \
        const float t   = __saturatef(dot);                \
        const float xp  = fmaf(-t, a.w, xs);               \
        const float yp  = fmaf(-t, bb.x, bb.y);            \
        const float d   = fmaf(xp, xp, yp * yp);           \
        (MN) = fminf((MN), d);                             \
    } while (0)

        PIX(gx0, mn0);
        PIX(gx1, mn1);
        PIX(gx2, mn2);
        PIX(gx3, mn3);
#undef PIX
    }

    // ---- epilogue: sign from parity, sigmoid, store ----
    // All-culled => FLT_MAX => exact 0/1, matching the saturated reference.
    float* op = out + ((size_t)b * NH + row) * NW + lane;
#define EMIT(PM, MN, K) do {                                         \
        const float io = ((PM >> lane) & 1u) ? 1.0f : -1.0f;         \
        const float v  = (MN) * io;                                  \
        op[(K) * 32] = __fdividef(1.0f, 1.0f + __expf(-v));          \
    } while (0)
    EMIT(pm0, mn0, 0);
    EMIT(pm1, mn1, 1);
    EMIT(pm2, mn2, 2);
    EMIT(pm3, mn3, 3);
#undef EMIT
}

}  // namespace

extern "C" void kernel_launch(void* const* d_in, const int* in_sizes, int n_in,
                              void* d_out, int out_size) {
    const float* verts = (const float*)d_in[0];
    float* out = (float*)d_out;
    dim3 grid(NH / RPB, NB);   // 32 x 32 = 1024 blocks, 4 warps each
    soft_poly_kernel<<<grid, 128>>>(verts, out);
}

// round 13
// speedup vs baseline: 1.0560x; 1.0560x over previous
#include <cuda_runtime.h>
#include <cstdint>
#include <math.h>

// SoftPolygon B=32, P=32, 128x128.  out[b,y,x] = sigmoid(min_seg_sq * io)
//
// v13: v11 config (warp = half-row, 2 px/lane, 8192 warps, exact cull) with
//  - FAST division everywhere. Parity-safety proof: a parity flip needs
//    |gx - xint| < div_err, but the crossing point lies ON that edge, so the
//    pixel is within div_err of the polygon boundary -> both outputs ~0.5,
//    per-flip error ~ err^2 ~ 1e-10 << 1e-3 gate.
//  - intersection part of the cull via shfl of the neighbor lane's crossing
//    flag (the parity edge of lane i+1 IS the distance edge of lane i).
//  - 64-thread blocks (block = row), 4096 blocks for better balance.

namespace {

constexpr int NB  = 32;
constexpr int NP  = 32;
constexpr int NH  = 128;
constexpr int NW  = 128;
constexpr float CULL_T = 25.0f;   // sq-distance saturation threshold (5 px)

__global__ __launch_bounds__(64) void soft_poly_kernel(
    const float* __restrict__ verts,   // (B, P, 2)
    float* __restrict__ out)           // (B, H, W)
{
    const int b    = blockIdx.y;
    const int row  = blockIdx.x;
    const int tid  = threadIdx.x;
    const int hp   = tid >> 5;         // column half 0..1
    const int lane = tid & 31;
    const float gy = (float)row;

    __shared__ float  vbuf[NP * 2];    // interleaved x,y
    __shared__ float4 sA[2][NP];       // per-warp: {x1, dx*inv, ys1*dy*inv, dx}
    __shared__ float2 sB[2][NP];       // per-warp: {dy, ys1}

    vbuf[tid] = verts[(size_t)b * NP * 2 + tid];
    __syncthreads();

    // ---- per-(row, edge) precompute; edge = lane; warp-local ----
    const unsigned full = 0xffffffffu;
    const float sxa = (float)(hp * 64);
    const float sxb = sxa + 63.0f;
    unsigned int pmA, pmB;   // parity words for this warp's 2 column groups
    unsigned int bits;       // keep-mask of edges relevant to this span
    {
        const int i  = lane;
        const int jp = (i + NP - 1) & (NP - 1);   // prev vertex (roll +1)
        const int kn = (i + 1) & (NP - 1);        // next vertex (roll -1)
        const float fx = vbuf[2 * i],  fy = vbuf[2 * i + 1];
        const float tx = vbuf[2 * jp], ty = vbuf[2 * jp + 1];
        const float x2 = vbuf[2 * kn], y2 = vbuf[2 * kn + 1];

        // crossing threshold (fast div; flips only ulp-boundary pixels whose
        // distance to the boundary is then ~ulp -> error ~ulp^2)
        const bool cond = (fy > gy) != (ty > gy);
        float xint = __fdividef(__fmul_rn(tx - fx, gy - fy), ty - fy) + fx;
        // crossing of parity-edge (jp->i) within THIS warp's span:
        // that edge is the distance edge of lane jp; shared via shfl below.
        const bool crossFlag = cond && (xint >= sxa) && (xint <= sxb);
        if (!cond) xint = -1.0f;
        // #columns c in [0,128) with (float)c < xint
        const float xc = fminf(fmaxf(ceilf(xint), 0.0f), 128.0f);
        const int ci = (int)xc - hp * 64;   // relative to this warp's half

        const int nA = min(max(ci,      0), 32);
        const int nB = min(max(ci - 32, 0), 32);
        const unsigned int mA = (unsigned int)((1ull << nA) - 1ull);
        const unsigned int mB = (unsigned int)((1ull << nB) - 1ull);
        pmA = __reduce_xor_sync(full, mA);
        pmB = __reduce_xor_sync(full, mB);

        // segment-distance constants for edge (v_i -> v_{i+1})
        const float dx = x2 - fx, dy = y2 - fy;
        const float sq  = dx * dx + dy * dy + 1e-5f;
        const float inv = __fdividef(1.0f, sq);   // continuous path
        const float ys1 = gy - fy;
        const float ys2 = gy - y2;
        sA[hp][i] = make_float4(fx, dx * inv, ys1 * dy * inv, dx);
        sB[hp][i] = make_float2(dy, ys1);

        // ---- EXACT cull: dist(span segment, edge segment)^2 <= 25 ----
        // (1) edge endpoints -> span (horizontal segment at y=gy)
        const float ga  = fmaxf(0.0f, fmaxf(sxa - fx, fx - sxb));
        const float gb  = fmaxf(0.0f, fmaxf(sxa - x2, x2 - sxb));
        const float dva = fmaf(ga, ga, ys1 * ys1);
        const float dvb = fmaf(gb, gb, ys2 * ys2);
        // (2) span endpoints -> edge (point-to-segment)
        const float xsA = sxa - fx;
        const float tA  = __saturatef((xsA * dx + ys1 * dy) * inv);
        const float xpA = fmaf(-tA, dx, xsA);
        const float ypA = fmaf(-tA, dy, ys1);
        const float dpa = fmaf(xpA, xpA, ypA * ypA);
        const float xsB = sxb - fx;
        const float tB  = __saturatef((xsB * dx + ys1 * dy) * inv);
        const float xpB = fmaf(-tB, dx, xsB);
        const float ypB = fmaf(-tB, dy, ys1);
        const float dpb = fmaf(xpB, xpB, ypB * ypB);
        // (3) intersection: crossFlag of lane (i+1) is for edge (i -> i+1)
        const bool isect =
            (bool)__shfl_sync(full, (int)crossFlag, (lane + 1) & 31);

        const float best = fminf(fminf(dva, dvb), fminf(dpa, dpb));
        bits = __ballot_sync(full, isect || (best <= CULL_T));
    }
    __syncwarp();   // sA/sB written and read by the same warp

    // ---- mainloop: surviving edges only, 2 pixels per lane ----
    const float gx0 = sxa + (float)lane;
    const float gx1 = gx0 + 32.0f;
    float mn0 = 3.402823466e38f, mn1 = mn0;

    while (bits) {
        const int i = __ffs(bits) - 1;
        bits &= bits - 1;
        const float4 a  = sA[hp][i];
        const float2 bb = sB[hp][i];

#define PIX(GX, MN) do {                                   \
        const float xs  = (GX) - a.x;                      \
        const float dot = fmaf(xs, a.y, a.z);              \
        const float t   = __saturatef(dot);                \
        const float xp  = fmaf(-t, a.w, xs);               \
        const float yp  = fmaf(-t, bb.x, bb.y);            \
        const float d   = fmaf(xp, xp, yp * yp);           \
        (MN) = fminf((MN), d);                             \
    } while (0)

        PIX(gx0, mn0);
        PIX(gx1, mn1);
#undef PIX
    }

    // ---- epilogue: sign from parity, sigmoid, store ----
    // All-culled => FLT_MAX => exact 0/1, matching the saturated reference.
    float* op = out + ((size_t)b * NH + row) * NW + hp * 64 + lane;
    {
        const float io0 = ((pmA >> lane) & 1u) ? 1.0f : -1.0f;
        const float io1 = ((pmB >> lane) & 1u) ? 1.0f : -1.0f;
        const float v0  = mn0 * io0;
        const float v1  = mn1 * io1;
        op[0]  = __fdividef(1.0f, 1.0f + __expf(-v0));
        op[32] = __fdividef(1.0f, 1.0f + __expf(-v1));
    }
}

}  // namespace

extern "C" void kernel_launch(void* const* d_in, const int* in_sizes, int n_in,
                              void* d_out, int out_size) {
    const float* verts = (const float*)d_in[0];
    float* out = (float*)d_out;
    dim3 grid(NH, NB);   // 128 x 32 = 4096 blocks, 64 threads each
    soft_poly_kernel<<<grid, 64>>>(verts, out);
}

// round 14
// speedup vs baseline: 1.0760x; 1.0190x over previous
#include <cuda_runtime.h>
#include <cstdint>
#include <math.h>

// SoftPolygon B=32, P=32, 128x128.  out[b,y,x] = sigmoid(min_seg_sq * io)
//
// v14: v11 block shape (128 thr = 2 rows x 2 half-spans, 2048 blocks; best
//      bench shape) + v13 fast-div arithmetic + NEW compacted edge list:
//      kept lanes scatter their constants to slot popc(mask & lanemask_lt),
//      mainloop is a counted warp-uniform for-loop, 2 edges/iter.
//
//  - fast-div parity safety: a flip needs |gx-xint| < div_err, but the
//    crossing point lies ON that edge, so the pixel is within div_err of the
//    boundary -> both outputs ~0.5; per-flip error ~1e-10 << 1e-3.
//  - culled edges are >5px from every span pixel -> sigmoid saturated
//    within 1.4e-11; all-culled => FLT_MAX => exact 0/1.

namespace {

constexpr int NB  = 32;
constexpr int NP  = 32;
constexpr int NH  = 128;
constexpr int NW  = 128;
constexpr int RPB = 2;            // rows per block (2 warps per row)
constexpr float CULL_T = 25.0f;   // sq-distance saturation threshold (5 px)

__global__ __launch_bounds__(128) void soft_poly_kernel(
    const float* __restrict__ verts,   // (B, P, 2)
    float* __restrict__ out)           // (B, H, W)
{
    const int b    = blockIdx.y;
    const int row0 = blockIdx.x * RPB;
    const int tid  = threadIdx.x;
    const int w    = tid >> 5;         // warp 0..3
    const int lane = tid & 31;
    const int r    = w >> 1;           // local row 0..1
    const int hp   = w & 1;            // column half 0..1
    const int row  = row0 + r;
    const float gy = (float)row;

    __shared__ float  vbuf[NP * 2];    // interleaved x,y
    __shared__ float4 sA[4][NP];       // per-warp compacted {x1, dx*inv, c0, dx}
    __shared__ float2 sB[4][NP];       // per-warp compacted {dy, ys1}

    if (tid < NP * 2) vbuf[tid] = verts[(size_t)b * NP * 2 + tid];
    __syncthreads();

    // ---- per-(row, edge) precompute; edge = lane; warp-local ----
    const unsigned full = 0xffffffffu;
    const float sxa = (float)(hp * 64);
    const float sxb = sxa + 63.0f;
    unsigned int pmA, pmB;   // parity words for this warp's 2 column groups
    int nkeep;               // number of surviving edges (warp-uniform)
    {
        const int i  = lane;
        const int jp = (i + NP - 1) & (NP - 1);   // prev vertex (roll +1)
        const int kn = (i + 1) & (NP - 1);        // next vertex (roll -1)
        const float fx = vbuf[2 * i],  fy = vbuf[2 * i + 1];
        const float tx = vbuf[2 * jp], ty = vbuf[2 * jp + 1];
        const float x2 = vbuf[2 * kn], y2 = vbuf[2 * kn + 1];

        // crossing threshold (fast div; see header for flip-safety proof)
        const bool cond = (fy > gy) != (ty > gy);
        float xint = __fdividef(__fmul_rn(tx - fx, gy - fy), ty - fy) + fx;
        // crossing of parity-edge (jp->i) within THIS warp's span:
        // that edge is the distance edge of lane jp; shared via shfl below.
        const bool crossFlag = cond && (xint >= sxa) && (xint <= sxb);
        if (!cond) xint = -1.0f;
        // #columns c in [0,128) with (float)c < xint
        const float xc = fminf(fmaxf(ceilf(xint), 0.0f), 128.0f);
        const int ci = (int)xc - hp * 64;   // relative to this warp's half

        const int nA = min(max(ci,      0), 32);
        const int nB = min(max(ci - 32, 0), 32);
        const unsigned int mA = (unsigned int)((1ull << nA) - 1ull);
        const unsigned int mB = (unsigned int)((1ull << nB) - 1ull);
        pmA = __reduce_xor_sync(full, mA);
        pmB = __reduce_xor_sync(full, mB);

        // segment-distance constants for edge (v_i -> v_{i+1})
        const float dx = x2 - fx, dy = y2 - fy;
        const float sq  = dx * dx + dy * dy + 1e-5f;
        const float inv = __fdividef(1.0f, sq);   // continuous path
        const float ys1 = gy - fy;
        const float ys2 = gy - y2;

        // ---- EXACT cull: dist(span segment, edge segment)^2 <= 25 ----
        const float ga  = fmaxf(0.0f, fmaxf(sxa - fx, fx - sxb));
        const float gb  = fmaxf(0.0f, fmaxf(sxa - x2, x2 - sxb));
        const float dva = fmaf(ga, ga, ys1 * ys1);
        const float dvb = fmaf(gb, gb, ys2 * ys2);
        const float xsA = sxa - fx;
        const float tA  = __saturatef((xsA * dx + ys1 * dy) * inv);
        const float xpA = fmaf(-tA, dx, xsA);
        const float ypA = fmaf(-tA, dy, ys1);
        const float dpa = fmaf(xpA, xpA, ypA * ypA);
        const float xsB = sxb - fx;
        const float tB  = __saturatef((xsB * dx + ys1 * dy) * inv);
        const float xpB = fmaf(-tB, dx, xsB);
        const float ypB = fmaf(-tB, dy, ys1);
        const float dpb = fmaf(xpB, xpB, ypB * ypB);
        const bool isect =
            (bool)__shfl_sync(full, (int)crossFlag, (lane + 1) & 31);

        const float best = fminf(fminf(dva, dvb), fminf(dpa, dpb));
        const bool keep = isect || (best <= CULL_T);
        const unsigned int kmask = __ballot_sync(full, keep);
        nkeep = __popc(kmask);

        // compacted scatter: kept lane -> dense slot
        if (keep) {
            const int pos = __popc(kmask & ((1u << lane) - 1u));
            sA[w][pos] = make_float4(fx, dx * inv, ys1 * dy * inv, dx);
            sB[w][pos] = make_float2(dy, ys1);
        }
    }
    __syncwarp();   // sA/sB written and read by the same warp

    // ---- mainloop: counted loop over compacted edges, 2 per iteration ----
    const float gx0 = sxa + (float)lane;
    const float gx1 = gx0 + 32.0f;
    float mn0 = 3.402823466e38f, mn1 = mn0;

#define PIX(A, BB, GX, MN) do {                                \
        const float xs  = (GX) - (A).x;                        \
        const float dot = fmaf(xs, (A).y, (A).z);              \
        const float t   = __saturatef(dot);                    \
        const float xp  = fmaf(-t, (A).w, xs);                 \
        const float yp  = fmaf(-t, (BB).x, (BB).y);            \
        const float d   = fmaf(xp, xp, yp * yp);               \
        (MN) = fminf((MN), d);                                 \
    } while (0)

    int i = 0;
    for (; i + 2 <= nkeep; i += 2) {
        const float4 a0 = sA[w][i],     a1 = sA[w][i + 1];
        const float2 b0 = sB[w][i],     b1 = sB[w][i + 1];
        PIX(a0, b0, gx0, mn0);
        PIX(a0, b0, gx1, mn1);
        PIX(a1, b1, gx0, mn0);
        PIX(a1, b1, gx1, mn1);
    }
    if (i < nkeep) {
        const float4 a0 = sA[w][i];
        const float2 b0 = sB[w][i];
        PIX(a0, b0, gx0, mn0);
        PIX(a0, b0, gx1, mn1);
    }
#undef PIX

    // ---- epilogue: sign from parity, sigmoid, store ----
    float* op = out + ((size_t)b * NH + row) * NW + hp * 64 + lane;
    {
        const float io0 = ((pmA >> lane) & 1u) ? 1.0f : -1.0f;
        const float io1 = ((pmB >> lane) & 1u) ? 1.0f : -1.0f;
        const float v0  = mn0 * io0;
        const float v1  = mn1 * io1;
        op[0]  = __fdividef(1.0f, 1.0f + __expf(-v0));
        op[32] = __fdividef(1.0f, 1.0f + __expf(-v1));
    }
}

}  // namespace

extern "C" void kernel_launch(void* const* d_in, const int* in_sizes, int n_in,
                              void* d_out, int out_size) {
    const float* verts = (const float*)d_in[0];
    float* out = (float*)d_out;
    dim3 grid(NH / RPB, NB);   // 64 x 32 = 2048 blocks, 128 threads each
    soft_poly_kernel<<<grid, 128>>>(verts, out);
}

// round 15
// speedup vs baseline: 1.1012x; 1.0233x over previous
#include <cuda_runtime.h>
#include <cstdint>
#include <math.h>

// SoftPolygon B=32, P=32, 128x128.  out[b,y,x] = sigmoid(min_seg_sq * io)
//
// v15: v14 skeleton (2048 x 128thr, warp = half-row, compacted edge list) +
//  - CULL_T = 9 (3px band): saturation error at margin e^-9 ~ 1.2e-4 abs on
//    band pixels only -> rel-norm ~1e-5.
//  - dvb via shfl (lane i+1's vertex-to-span distance IS edge i's dvb).
//  - adjacent-column pixel pairs (cols 2l, 2l+1) -> one float2 store; parity
//    pair extracted from 64-bit concat of the two parity words.
//  - sigmoid via tanh.approx.f32 (saturates exactly; band err <= 2.4e-4 abs).
//  - fast division everywhere (parity flip error ~ulp^2, proof in R13).

namespace {

constexpr int NB  = 32;
constexpr int NP  = 32;
constexpr int NH  = 128;
constexpr int NW  = 128;
constexpr int RPB = 2;            // rows per block (2 warps per row)
constexpr float CULL_T = 9.0f;    // sq-distance saturation threshold (3 px)

__device__ __forceinline__ float sigmoid_fast(float v) {
    float t;
    asm("tanh.approx.f32 %0, %1;" : "=f"(t) : "f"(0.5f * v));
    return fmaf(0.5f, t, 0.5f);
}

__global__ __launch_bounds__(128) void soft_poly_kernel(
    const float* __restrict__ verts,   // (B, P, 2)
    float* __restrict__ out)           // (B, H, W)
{
    const int b    = blockIdx.y;
    const int row0 = blockIdx.x * RPB;
    const int tid  = threadIdx.x;
    const int w    = tid >> 5;         // warp 0..3
    const int lane = tid & 31;
    const int r    = w >> 1;           // local row 0..1
    const int hp   = w & 1;            // column half 0..1
    const int row  = row0 + r;
    const float gy = (float)row;

    __shared__ float  vbuf[NP * 2];    // interleaved x,y
    __shared__ float4 sA[4][NP];       // per-warp compacted {x1, dx*inv, c0, dx}
    __shared__ float2 sB[4][NP];       // per-warp compacted {dy, ys1}

    if (tid < NP * 2) vbuf[tid] = verts[(size_t)b * NP * 2 + tid];
    __syncthreads();

    // ---- per-(row, edge) precompute; edge = lane; warp-local ----
    const unsigned full = 0xffffffffu;
    const float sxa = (float)(hp * 64);
    const float sxb = sxa + 63.0f;
    unsigned int pmA, pmB;   // parity words: cols [sxa, sxa+32), [sxa+32, sxa+64)
    int nkeep;               // surviving edge count (warp-uniform)
    {
        const int i  = lane;
        const int jp = (i + NP - 1) & (NP - 1);   // prev vertex (roll +1)
        const int kn = (i + 1) & (NP - 1);        // next vertex (roll -1)
        const float fx = vbuf[2 * i],  fy = vbuf[2 * i + 1];
        const float tx = vbuf[2 * jp], ty = vbuf[2 * jp + 1];
        const float x2 = vbuf[2 * kn], y2 = vbuf[2 * kn + 1];

        // crossing threshold (fast div; flip-safety: crossing point lies on
        // the edge, so an affected pixel is within div_err of the boundary)
        const bool cond = (fy > gy) != (ty > gy);
        float xint = __fdividef(__fmul_rn(tx - fx, gy - fy), ty - fy) + fx;
        // crossing of parity-edge (jp->i) within THIS warp's span:
        // that edge is the distance edge of lane jp; shared via shfl below.
        const bool crossFlag = cond && (xint >= sxa) && (xint <= sxb);
        if (!cond) xint = -1.0f;
        // #columns c in [0,128) with (float)c < xint
        const float xc = fminf(fmaxf(ceilf(xint), 0.0f), 128.0f);
        const int ci = (int)xc - hp * 64;   // relative to this warp's half

        const int nA = min(max(ci,      0), 32);
        const int nB = min(max(ci - 32, 0), 32);
        const unsigned int mA = (unsigned int)((1ull << nA) - 1ull);
        const unsigned int mB = (unsigned int)((1ull << nB) - 1ull);
        pmA = __reduce_xor_sync(full, mA);
        pmB = __reduce_xor_sync(full, mB);

        // segment-distance constants for edge (v_i -> v_{i+1})
        const float dx = x2 - fx, dy = y2 - fy;
        const float sq  = dx * dx + dy * dy + 1e-5f;
        const float inv = __fdividef(1.0f, sq);   // continuous path
        const float ys1 = gy - fy;

        // ---- EXACT cull vs dist^2 <= CULL_T ----
        // (1) edge endpoints -> span:  dva here; dvb = next lane's dva
        const float ga  = fmaxf(0.0f, fmaxf(sxa - fx, fx - sxb));
        const float dva = fmaf(ga, ga, ys1 * ys1);
        const float dvb = __shfl_sync(full, dva, (lane + 1) & 31);
        // (2) span endpoints -> edge (point-to-segment)
        const float xsA = sxa - fx;
        const float tA  = __saturatef((xsA * dx + ys1 * dy) * inv);
        const float xpA = fmaf(-tA, dx, xsA);
        const float ypA = fmaf(-tA, dy, ys1);
        const float dpa = fmaf(xpA, xpA, ypA * ypA);
        const float xsB = sxb - fx;
        const float tB  = __saturatef((xsB * dx + ys1 * dy) * inv);
        const float xpB = fmaf(-tB, dx, xsB);
        const float ypB = fmaf(-tB, dy, ys1);
        const float dpb = fmaf(xpB, xpB, ypB * ypB);
        // (3) intersection: crossFlag of lane (i+1) is for edge (i -> i+1)
        const bool isect =
            (bool)__shfl_sync(full, (int)crossFlag, (lane + 1) & 31);

        const float best = fminf(fminf(dva, dvb), fminf(dpa, dpb));
        const bool keep = isect || (best <= CULL_T);
        const unsigned int kmask = __ballot_sync(full, keep);
        nkeep = __popc(kmask);

        if (keep) {   // compacted scatter: kept lane -> dense slot
            const int pos = __popc(kmask & ((1u << lane) - 1u));
            sA[w][pos] = make_float4(fx, dx * inv, ys1 * dy * inv, dx);
            sB[w][pos] = make_float2(dy, ys1);
        }
    }
    __syncwarp();   // sA/sB written and read by the same warp

    // ---- mainloop: compacted edges, adjacent-column pixel pair per lane ----
    const float gx0 = sxa + (float)(2 * lane);
    const float gx1 = gx0 + 1.0f;
    float mn0 = 3.402823466e38f, mn1 = mn0;

#define PIX(A, BB, GX, MN) do {                                \
        const float xs  = (GX) - (A).x;                        \
        const float dot = fmaf(xs, (A).y, (A).z);              \
        const float t   = __saturatef(dot);                    \
        const float xp  = fmaf(-t, (A).w, xs);                 \
        const float yp  = fmaf(-t, (BB).x, (BB).y);            \
        const float d   = fmaf(xp, xp, yp * yp);               \
        (MN) = fminf((MN), d);                                 \
    } while (0)

    int i = 0;
    for (; i + 2 <= nkeep; i += 2) {
        const float4 a0 = sA[w][i],     a1 = sA[w][i + 1];
        const float2 b0 = sB[w][i],     b1 = sB[w][i + 1];
        PIX(a0, b0, gx0, mn0);
        PIX(a0, b0, gx1, mn1);
        PIX(a1, b1, gx0, mn0);
        PIX(a1, b1, gx1, mn1);
    }
    if (i < nkeep) {
        const float4 a0 = sA[w][i];
        const float2 b0 = sB[w][i];
        PIX(a0, b0, gx0, mn0);
        PIX(a0, b0, gx1, mn1);
    }
#undef PIX

    // ---- epilogue: parity pair from 64-bit concat, fast sigmoid, STG.64 ----
    const unsigned long long p64 =
        (unsigned long long)pmA | ((unsigned long long)pmB << 32);
    const unsigned int pair = (unsigned int)(p64 >> (2 * lane)) & 3u;
    const float io0 = (pair & 1u) ? 1.0f : -1.0f;
    const float io1 = (pair & 2u) ? 1.0f : -1.0f;

    float2* op = (float2*)(out + ((size_t)b * NH + row) * NW + hp * 64) + lane;
    *op = make_float2(sigmoid_fast(mn0 * io0), sigmoid_fast(mn1 * io1));
}

}  // namespace

extern "C" void kernel_launch(void* const* d_in, const int* in_sizes, int n_in,
                              void* d_out, int out_size) {
    const float* verts = (const float*)d_in[0];
    float* out = (float*)d_out;
    dim3 grid(NH / RPB, NB);   // 64 x 32 = 2048 blocks, 128 threads each
    soft_poly_kernel<<<grid, 128>>>(verts, out);
}